// round 1
// baseline (speedup 1.0000x reference)
#include <cuda_runtime.h>
#include <stdint.h>

// Problem dims (fixed by dataset)
#define Bb 8
#define Cc 2048
#define Nn 8000
#define Hh 256
#define Oo 1000
#define CLAMP_V 1e4f

// Scratch (static device globals; runtime allocation is forbidden)
__device__ __align__(16) float g_h0[(size_t)Bb * Hh * Nn];   // 65.5 MB
__device__ __align__(16) float g_h1[(size_t)Bb * Hh * Nn];   // 65.5 MB
__device__ __align__(16) float g_y [(size_t)Bb * Oo * Nn];   // 256 MB
__device__ __align__(16) float g_mask[Bb * Nn];
__device__ __align__(16) float g_coef[Bb * 128];

// ---------------------------------------------------------------------------
// mask[b,n] = (max_c x[b,c,n] > 0) ? 1 : 0
// ---------------------------------------------------------------------------
__global__ void mask_kernel(const float* __restrict__ x) {
    int n = blockIdx.x * blockDim.x + threadIdx.x;
    int b = blockIdx.y;
    if (n >= Nn) return;
    const float* p = x + (size_t)b * Cc * Nn + n;
    float m = -3.402823466e38f;
#pragma unroll 8
    for (int c = 0; c < Cc; ++c) m = fmaxf(m, p[(size_t)c * Nn]);
    g_mask[b * Nn + n] = (m > 0.0f) ? 1.0f : 0.0f;
}

// ---------------------------------------------------------------------------
// Per-batch rank coefficients for the top-k weighted average.
// pred[b,o] = sum_j t_sorted[j] * coef[b][j],
// coef[b][j] = mask[b,j] * sum_{k in {10,25,50,100}, k>j} 1/(4*den_k),
// den_k = sum_{i<k} mask[b,i]
// ---------------------------------------------------------------------------
__global__ void coef_kernel() {
    int b = threadIdx.x;
    if (b >= Bb) return;
    float s = 0.f, d10 = 0.f, d25 = 0.f, d50 = 0.f;
    for (int j = 0; j < 100; ++j) {
        s += g_mask[b * Nn + j];
        if (j == 9)  d10 = s;
        if (j == 24) d25 = s;
        if (j == 49) d50 = s;
    }
    float d100 = s;
    for (int j = 0; j < 100; ++j) {
        float w = 0.25f / d100;
        if (j < 50) w += 0.25f / d50;
        if (j < 25) w += 0.25f / d25;
        if (j < 10) w += 0.25f / d10;
        g_coef[b * 128 + j] = g_mask[b * Nn + j] * w;
    }
}

// ---------------------------------------------------------------------------
// Tiled SGEMM: C[b][m][n] = act(A[m][k] * B[b][k][n] + bias[m])
// Block tile 64(m) x 64(n), BK=16, 256 threads, 4x4 microtile.
// SRC: 0 = x (param), 1 = g_h0, 2 = g_h1
// DST: 0 = g_h0, 1 = g_h1, 2 = g_y
// MODE: 0 = clamp(relu(.), 1e4), 1 = multiply by g_mask[b][n]
// ---------------------------------------------------------------------------
template<int SRC, int DST, int MODE>
__global__ __launch_bounds__(256)
void gemm_kernel(const float* __restrict__ A, const float* __restrict__ Xin,
                 const float* __restrict__ bias, int M, int K)
{
    const int b  = blockIdx.z;
    const int n0 = blockIdx.x * 64;
    const int m0 = blockIdx.y * 64;

    const float* Bp = ((SRC == 0) ? Xin : (SRC == 1 ? g_h0 : g_h1)) + (size_t)b * K * Nn;
    float*       Cp = ((DST == 0) ? g_h0 : (DST == 1 ? g_h1 : g_y)) + (size_t)b * M * Nn;

    __shared__ __align__(16) float As[16][64];   // transposed A tile: As[k][m]
    __shared__ __align__(16) float Bs[16][64];   // Bs[k][n]

    const int tid = threadIdx.x;
    const int tx  = tid & 15;        // n-direction thread coord
    const int ty  = tid >> 4;        // m-direction thread coord

    const int arow = tid >> 2;       // 0..63  (m within tile)
    const int ak   = (tid & 3) * 4;  // 0,4,8,12 (k within tile)
    const int brow = tid >> 4;       // 0..15  (k within tile)
    const int bc   = (tid & 15) * 4; // 0..60  (n within tile)

    float acc[4][4];
#pragma unroll
    for (int i = 0; i < 4; ++i)
#pragma unroll
        for (int j = 0; j < 4; ++j) acc[i][j] = 0.f;

    for (int k0 = 0; k0 < K; k0 += 16) {
        float4 av = make_float4(0.f, 0.f, 0.f, 0.f);
        if (m0 + arow < M)
            av = *(const float4*)(A + (size_t)(m0 + arow) * K + k0 + ak);
        float4 bv = *(const float4*)(Bp + (size_t)(k0 + brow) * Nn + n0 + bc);

        __syncthreads();
        As[ak + 0][arow] = av.x;
        As[ak + 1][arow] = av.y;
        As[ak + 2][arow] = av.z;
        As[ak + 3][arow] = av.w;
        *(float4*)&Bs[brow][bc] = bv;
        __syncthreads();

#pragma unroll
        for (int k = 0; k < 16; ++k) {
            float4 a = *(const float4*)&As[k][ty * 4];
            float4 v = *(const float4*)&Bs[k][tx * 4];
            acc[0][0] += a.x * v.x; acc[0][1] += a.x * v.y; acc[0][2] += a.x * v.z; acc[0][3] += a.x * v.w;
            acc[1][0] += a.y * v.x; acc[1][1] += a.y * v.y; acc[1][2] += a.y * v.z; acc[1][3] += a.y * v.w;
            acc[2][0] += a.z * v.x; acc[2][1] += a.z * v.y; acc[2][2] += a.z * v.z; acc[2][3] += a.z * v.w;
            acc[3][0] += a.w * v.x; acc[3][1] += a.w * v.y; acc[3][2] += a.w * v.z; acc[3][3] += a.w * v.w;
        }
    }

#pragma unroll
    for (int i = 0; i < 4; ++i) {
        int m = m0 + ty * 4 + i;
        if (m < M) {
            float bb = bias[m];
            float4 r = make_float4(acc[i][0] + bb, acc[i][1] + bb,
                                   acc[i][2] + bb, acc[i][3] + bb);
            if (MODE == 0) {
                r.x = fminf(fmaxf(r.x, 0.f), CLAMP_V);
                r.y = fminf(fmaxf(r.y, 0.f), CLAMP_V);
                r.z = fminf(fmaxf(r.z, 0.f), CLAMP_V);
                r.w = fminf(fmaxf(r.w, 0.f), CLAMP_V);
            } else {
                const float4 mk = *(const float4*)&g_mask[b * Nn + n0 + tx * 4];
                r.x *= mk.x; r.y *= mk.y; r.z *= mk.z; r.w *= mk.w;
            }
            *(float4*)(Cp + (size_t)m * Nn + n0 + tx * 4) = r;
        }
    }
}

// ---------------------------------------------------------------------------
// Exact top-100 per (b,o) row via MSB-first 8-bit radix select on
// order-preserving uint keys, then rank-sort the 100 winners and dot
// with the per-batch rank coefficients.
// ---------------------------------------------------------------------------
__global__ __launch_bounds__(256)
void topk_kernel(float* __restrict__ out) {
    const int row = blockIdx.x;        // b*Oo + o
    const int b   = row / Oo;
    const int tid = threadIdx.x;

    __shared__ uint32_t su[Nn];        // 32000 B
    __shared__ uint32_t hist[256];
    __shared__ uint32_t s_sel[2];
    __shared__ uint32_t s_cnt;
    __shared__ uint32_t buf[128];
    __shared__ uint32_t srt[128];
    __shared__ float    partial[256];

    const float* yp = g_y + (size_t)row * Nn;
    for (int i = tid; i < Nn; i += 256) {
        uint32_t bits = __float_as_uint(yp[i]);
        su[i] = (bits & 0x80000000u) ? ~bits : (bits | 0x80000000u);
    }

    uint32_t prefix = 0, hiMask = 0;
    int K = 100;
    for (int level = 3; level >= 0; --level) {
        const int shift = level * 8;
        hist[tid] = 0;
        __syncthreads();   // orders su[] fill on first pass + hist zero
        for (int i = tid; i < Nn; i += 256) {
            uint32_t v = su[i];
            if ((v & hiMask) == prefix) atomicAdd(&hist[(v >> shift) & 255u], 1u);
        }
        __syncthreads();
        if (tid == 0) {
            int cum = 0, bin = 255;
            for (; bin > 0; --bin) {
                int c = (int)hist[bin];
                if (cum + c >= K) break;
                cum += c;
            }
            s_sel[0] = (uint32_t)bin;
            s_sel[1] = (uint32_t)(K - cum);
        }
        __syncthreads();
        prefix |= (s_sel[0] << shift);
        K = (int)s_sel[1];
        hiMask |= (0xFFu << shift);
        __syncthreads();
    }
    const uint32_t thr = prefix;   // exact key of the 100th-largest (ties at this value)

    if (tid == 0) s_cnt = 0;
    __syncthreads();
    for (int i = tid; i < Nn; i += 256) {
        uint32_t v = su[i];
        if (v > thr) {
            uint32_t idx = atomicAdd(&s_cnt, 1u);
            if (idx < 128u) buf[idx] = v;
        }
    }
    __syncthreads();
    int g = (int)min(s_cnt, 100u);
    for (int j = g + tid; j < 100; j += 256) buf[j] = thr;  // fill ties
    __syncthreads();

    if (tid < 100) {
        uint32_t v = buf[tid];
        int rank = 0;
#pragma unroll 4
        for (int j = 0; j < 100; ++j) {
            uint32_t w = buf[j];
            rank += (w > v) || (w == v && j < tid);
        }
        srt[rank] = v;
    }
    __syncthreads();

    float t = 0.f;
    if (tid < 100) {
        uint32_t u = srt[tid];
        uint32_t bits = (u & 0x80000000u) ? (u & 0x7FFFFFFFu) : ~u;
        t = __uint_as_float(bits) * g_coef[b * 128 + tid];
    }
    partial[tid] = t;
    __syncthreads();
    for (int s = 128; s > 0; s >>= 1) {
        if (tid < s) partial[tid] += partial[tid + s];
        __syncthreads();
    }
    if (tid == 0) out[row] = partial[0];
}

// ---------------------------------------------------------------------------
extern "C" void kernel_launch(void* const* d_in, const int* in_sizes, int n_in,
                              void* d_out, int out_size) {
    const float* x  = (const float*)d_in[0];
    const float* W0 = (const float*)d_in[1];
    const float* b0 = (const float*)d_in[2];
    const float* W1 = (const float*)d_in[3];
    const float* b1 = (const float*)d_in[4];
    const float* W2 = (const float*)d_in[5];
    const float* b2 = (const float*)d_in[6];
    float* out = (float*)d_out;

    (void)in_sizes; (void)n_in; (void)out_size;

    mask_kernel<<<dim3((Nn + 255) / 256, Bb), 256>>>(x);
    coef_kernel<<<1, 32>>>();

    // h0 = clamp(relu(W0 @ x + b0))
    gemm_kernel<0, 0, 0><<<dim3(Nn / 64, Hh / 64, Bb), 256>>>(W0, x, b0, Hh, Cc);
    // h1 = clamp(relu(W1 @ h0 + b1))
    gemm_kernel<1, 1, 0><<<dim3(Nn / 64, Hh / 64, Bb), 256>>>(W1, x, b1, Hh, Hh);
    // y = (W2 @ h1 + b2) * mask
    gemm_kernel<2, 2, 1><<<dim3(Nn / 64, (Oo + 63) / 64, Bb), 256>>>(W2, x, b2, Oo, Hh);

    topk_kernel<<<Bb * Oo, 256>>>(out);
}

// round 6
// speedup vs baseline: 3.2122x; 3.2122x over previous
#include <cuda_runtime.h>
#include <cuda_fp16.h>
#include <stdint.h>

#define Bb 8
#define Cc 2048
#define Nn 8000
#define Hh 256
#define Oo 1000
#define Op 1024
#define NTILE 63
#define STAGE_A 20480            // 256 rows x 80B (32 f16 + 16B pad)
#define STAGE_B 8704             // 32 k-rows x 272B (128 f16 + 16B pad)
#define STAGE_BYTES (STAGE_A + STAGE_B)
#define DYN_SMEM (2 * STAGE_BYTES)

__device__ __align__(16) __half g_W0h[Hh * Cc];
__device__ __align__(16) __half g_W1h[Hh * Hh];
__device__ __align__(16) __half g_W2h[Op * Hh];
__device__ __align__(16) __half g_xh[(size_t)Bb * Cc * Nn];
__device__ __align__(16) __half g_h0[(size_t)Bb * Hh * Nn];
__device__ __align__(16) __half g_h1[(size_t)Bb * Hh * Nn];
__device__ __align__(16) float  g_y [(size_t)Bb * Oo * Nn];
__device__ float g_mask[Bb * Nn];
__device__ float g_coef[Bb * 128];

__device__ __forceinline__ void ldm_x4(uint32_t* r, const void* p) {
    uint32_t a = (uint32_t)__cvta_generic_to_shared(p);
    asm volatile("ldmatrix.sync.aligned.m8n8.x4.shared.b16 {%0,%1,%2,%3}, [%4];\n"
                 : "=r"(r[0]), "=r"(r[1]), "=r"(r[2]), "=r"(r[3]) : "r"(a));
}
__device__ __forceinline__ void ldm_x4t(uint32_t* r, const void* p) {
    uint32_t a = (uint32_t)__cvta_generic_to_shared(p);
    asm volatile("ldmatrix.sync.aligned.m8n8.x4.trans.shared.b16 {%0,%1,%2,%3}, [%4];\n"
                 : "=r"(r[0]), "=r"(r[1]), "=r"(r[2]), "=r"(r[3]) : "r"(a));
}
__device__ __forceinline__ void mma16816(float* d, const uint32_t* a, uint32_t b0, uint32_t b1) {
    asm volatile("mma.sync.aligned.m16n8k16.row.col.f32.f16.f16.f32 "
                 "{%0,%1,%2,%3}, {%4,%5,%6,%7}, {%8,%9}, {%0,%1,%2,%3};\n"
                 : "+f"(d[0]), "+f"(d[1]), "+f"(d[2]), "+f"(d[3])
                 : "r"(a[0]), "r"(a[1]), "r"(a[2]), "r"(a[3]), "r"(b0), "r"(b1));
}
__device__ __forceinline__ uint32_t h2u(__half2 h) { return *reinterpret_cast<uint32_t*>(&h); }

// ---------------------------------------------------------------------------
// C[o(256), n(128)] = W[o][K] x B[k][n], fp16 in, fp32 accum.
// Register-double-buffered synchronous pipeline (LDG uint4 -> STS -> ldmatrix).
// L=1: B=g_xh -> h0 (relu/clamp, fp16). L=2: h0 -> h1. L=3: -> y fp32*mask+bias.
// ---------------------------------------------------------------------------
template <int L>
__global__ __launch_bounds__(512, 1) void mma_gemm(const float* __restrict__ bias) {
    constexpr int K = (L == 1) ? Cc : Hh;
    constexpr int NIT = K / 32;
    extern __shared__ __align__(16) char dyn[];

    const int tid = threadIdx.x, lane = tid & 31, warp = tid >> 5;
    const int wm = warp >> 2, wn = warp & 3;
    const int b = blockIdx.z, n0 = blockIdx.x * 128, o0 = blockIdx.y * 256;

    const __half* Wh = (L == 1) ? g_W0h : (L == 2) ? g_W1h : g_W2h;
    const __half* Bsrc = ((L == 1) ? g_xh : (L == 2) ? g_h0 : g_h1)
                         + (size_t)b * ((L == 1) ? Cc : Hh) * Nn;

    const int ar0 = tid >> 2, aseg = tid & 3;
    const int br = tid >> 4, bseg = tid & 15;
    const int bn = n0 + bseg * 8;
    uint4 ra0, ra1, rb;

    auto ldg = [&](int kk) {
        const int k0 = kk * 32;
        ra0 = *(const uint4*)(Wh + (size_t)(o0 + ar0) * K + k0 + aseg * 8);
        ra1 = *(const uint4*)(Wh + (size_t)(o0 + ar0 + 128) * K + k0 + aseg * 8);
        rb = (bn < Nn) ? *(const uint4*)(Bsrc + (size_t)(k0 + br) * Nn + bn)
                       : make_uint4(0u, 0u, 0u, 0u);
    };
    auto sts = [&](int buf) {
        char* s = dyn + buf * STAGE_BYTES;
        *(uint4*)(s + ar0 * 80 + aseg * 16) = ra0;
        *(uint4*)(s + (ar0 + 128) * 80 + aseg * 16) = ra1;
        *(uint4*)(s + STAGE_A + br * 272 + bseg * 16) = rb;
    };

    float d[4][4][4];
#pragma unroll
    for (int i = 0; i < 4; ++i)
#pragma unroll
        for (int j = 0; j < 4; ++j) { d[i][j][0]=0.f; d[i][j][1]=0.f; d[i][j][2]=0.f; d[i][j][3]=0.f; }

    ldg(0); sts(0);
    if (NIT > 1) ldg(1);
    __syncthreads();

#pragma unroll 1
    for (int k = 0; k < NIT; ++k) {
        const int cur = k & 1;
        if (k + 1 < NIT) sts(1 - cur);
        if (k + 2 < NIT) ldg(k + 2);
        {
            char* sa = dyn + cur * STAGE_BYTES;
            char* aB = sa + (wm * 64 + (lane & 15)) * 80 + ((lane >> 4) << 4);
            char* bB = sa + STAGE_A + (((lane >> 3) & 1) * 8 + (lane & 7)) * 272
                     + (wn * 32 + ((lane >> 4) << 3)) * 2;
#pragma unroll
            for (int s = 0; s < 2; ++s) {
                uint32_t a[4][4];
#pragma unroll
                for (int mf = 0; mf < 4; ++mf) ldm_x4(a[mf], aB + mf * 16 * 80 + s * 32);
#pragma unroll
                for (int nf2 = 0; nf2 < 2; ++nf2) {
                    uint32_t bq[4];
                    ldm_x4t(bq, bB + s * 16 * 272 + nf2 * 32);
#pragma unroll
                    for (int mf = 0; mf < 4; ++mf) {
                        mma16816(d[mf][nf2 * 2],     a[mf], bq[0], bq[1]);
                        mma16816(d[mf][nf2 * 2 + 1], a[mf], bq[2], bq[3]);
                    }
                }
            }
        }
        __syncthreads();
    }

    if (L <= 2) {
        __half* hout = ((L == 1) ? g_h0 : g_h1) + (size_t)b * Hh * Nn;
#pragma unroll
        for (int mf = 0; mf < 4; ++mf) {
            int o = wm * 64 + mf * 16 + (lane >> 2);
            float bs0 = bias[o], bs1 = bias[o + 8];
#pragma unroll
            for (int nf = 0; nf < 4; ++nf) {
                int n = n0 + wn * 32 + nf * 8 + (lane & 3) * 2;
                if (n < Nn) {
                    float v0 = fminf(fmaxf(d[mf][nf][0] + bs0, 0.f), 1e4f);
                    float v1 = fminf(fmaxf(d[mf][nf][1] + bs0, 0.f), 1e4f);
                    float v2 = fminf(fmaxf(d[mf][nf][2] + bs1, 0.f), 1e4f);
                    float v3 = fminf(fmaxf(d[mf][nf][3] + bs1, 0.f), 1e4f);
                    *(uint32_t*)(hout + (size_t)o * Nn + n)       = h2u(__floats2half2_rn(v0, v1));
                    *(uint32_t*)(hout + (size_t)(o + 8) * Nn + n) = h2u(__floats2half2_rn(v2, v3));
                }
            }
        }
    } else {
        float* yp = g_y + (size_t)b * Oo * Nn;
#pragma unroll
        for (int mf = 0; mf < 4; ++mf) {
            int o = o0 + wm * 64 + mf * 16 + (lane >> 2);
#pragma unroll
            for (int nf = 0; nf < 4; ++nf) {
                int n = n0 + wn * 32 + nf * 8 + (lane & 3) * 2;
                if (n < Nn) {
                    float mk0 = g_mask[b * Nn + n], mk1 = g_mask[b * Nn + n + 1];
                    if (o < Oo) {
                        float bs = bias[o];
                        *(float2*)(yp + (size_t)o * Nn + n) =
                            make_float2((d[mf][nf][0] + bs) * mk0, (d[mf][nf][1] + bs) * mk1);
                    }
                    if (o + 8 < Oo) {
                        float bs = bias[o + 8];
                        *(float2*)(yp + (size_t)(o + 8) * Nn + n) =
                            make_float2((d[mf][nf][2] + bs) * mk0, (d[mf][nf][3] + bs) * mk1);
                    }
                }
            }
        }
    }
}

// x fp32 -> fp16 flat copy (8 elems/thread)
__global__ __launch_bounds__(256) void xcvt_kernel(const float* __restrict__ x) {
    size_t i = ((size_t)blockIdx.x * 256 + threadIdx.x) * 8;
    if (i >= (size_t)Bb * Cc * Nn) return;
    float4 a = *(const float4*)(x + i);
    float4 c = *(const float4*)(x + i + 4);
    uint4 o;
    o.x = h2u(__floats2half2_rn(a.x, a.y)); o.y = h2u(__floats2half2_rn(a.z, a.w));
    o.z = h2u(__floats2half2_rn(c.x, c.y)); o.w = h2u(__floats2half2_rn(c.z, c.w));
    *(uint4*)(g_xh + i) = o;
}

__global__ void mask_kernel(const float* __restrict__ x) {
    int n = blockIdx.x * blockDim.x + threadIdx.x;
    int b = blockIdx.y;
    if (n >= Nn) return;
    const float* p = x + (size_t)b * Cc * Nn + n;
    float m = -3.402823466e38f;
#pragma unroll 8
    for (int c = 0; c < Cc; ++c) m = fmaxf(m, p[(size_t)c * Nn]);
    g_mask[b * Nn + n] = (m > 0.0f) ? 1.0f : 0.0f;
}

// FIXED: destination selected in DEVICE code (passing __device__ globals as
// host-side kernel args hands the kernel the host shadow address, which GB300
// ATS happily dereferences -> weights silently landed in host memory).
template <int WSEL>
__global__ void wconv_kernel(const float* __restrict__ W, int rows, int cols, int orows) {
    __half* outp = (WSEL == 0) ? g_W0h : (WSEL == 1) ? g_W1h : g_W2h;
    int i = blockIdx.x * 256 + threadIdx.x;
    if (i >= orows * cols) return;
    int r = i / cols, c = i - r * cols;
    outp[(size_t)r * cols + c] = __float2half_rn((r < rows) ? W[(size_t)r * cols + c] : 0.f);
}

__global__ void coef_kernel() {
    int b = threadIdx.x;
    if (b >= Bb) return;
    float s = 0.f, d10 = 0.f, d25 = 0.f, d50 = 0.f;
    for (int j = 0; j < 100; ++j) {
        s += g_mask[b * Nn + j];
        if (j == 9)  d10 = s;
        if (j == 24) d25 = s;
        if (j == 49) d50 = s;
    }
    float d100 = s;
    for (int j = 0; j < 100; ++j) {
        float w = 0.25f / d100;
        if (j < 50) w += 0.25f / d50;
        if (j < 25) w += 0.25f / d25;
        if (j < 10) w += 0.25f / d10;
        g_coef[b * 128 + j] = g_mask[b * Nn + j] * w;
    }
}

__global__ __launch_bounds__(256) void topk_kernel(float* __restrict__ out) {
    const int row = blockIdx.x, b = row / Oo, tid = threadIdx.x;
    __shared__ uint32_t su[Nn];
    __shared__ uint32_t hist[256];
    __shared__ uint32_t s_sel[2];
    __shared__ uint32_t s_cnt;
    __shared__ uint32_t buf[128];
    __shared__ uint32_t srt[128];
    __shared__ float partial[256];

    const float* yp = g_y + (size_t)row * Nn;
    for (int i = tid; i < Nn; i += 256) {
        uint32_t bits = __float_as_uint(yp[i]);
        su[i] = (bits & 0x80000000u) ? ~bits : (bits | 0x80000000u);
    }
    uint32_t prefix = 0, hiMask = 0;
    int K = 100;
    for (int level = 3; level >= 0; --level) {
        const int shift = level * 8;
        hist[tid] = 0;
        __syncthreads();
        for (int i = tid; i < Nn; i += 256) {
            uint32_t v = su[i];
            if ((v & hiMask) == prefix) atomicAdd(&hist[(v >> shift) & 255u], 1u);
        }
        __syncthreads();
        if (tid == 0) {
            int cum = 0, bin = 255;
            for (; bin > 0; --bin) {
                int c = (int)hist[bin];
                if (cum + c >= K) break;
                cum += c;
            }
            s_sel[0] = (uint32_t)bin; s_sel[1] = (uint32_t)(K - cum);
        }
        __syncthreads();
        prefix |= (s_sel[0] << shift);
        K = (int)s_sel[1];
        hiMask |= (0xFFu << shift);
        __syncthreads();
    }
    const uint32_t thr = prefix;
    if (tid == 0) s_cnt = 0;
    __syncthreads();
    for (int i = tid; i < Nn; i += 256) {
        uint32_t v = su[i];
        if (v > thr) {
            uint32_t idx = atomicAdd(&s_cnt, 1u);
            if (idx < 128u) buf[idx] = v;
        }
    }
    __syncthreads();
    int g = (int)min(s_cnt, 100u);
    for (int j = g + tid; j < 100; j += 256) buf[j] = thr;
    __syncthreads();
    if (tid < 100) {
        uint32_t v = buf[tid];
        int rank = 0;
#pragma unroll 4
        for (int j = 0; j < 100; ++j) {
            uint32_t w = buf[j];
            rank += (w > v) || (w == v && j < tid);
        }
        srt[rank] = v;
    }
    __syncthreads();
    float t = 0.f;
    if (tid < 100) {
        uint32_t u = srt[tid];
        uint32_t bits = (u & 0x80000000u) ? (u & 0x7FFFFFFFu) : ~u;
        t = __uint_as_float(bits) * g_coef[b * 128 + tid];
    }
    partial[tid] = t;
    __syncthreads();
    for (int s = 128; s > 0; s >>= 1) {
        if (tid < s) partial[tid] += partial[tid + s];
        __syncthreads();
    }
    if (tid == 0) out[row] = partial[0];
}

extern "C" void kernel_launch(void* const* d_in, const int* in_sizes, int n_in,
                              void* d_out, int out_size) {
    const float* x  = (const float*)d_in[0];
    const float* W0 = (const float*)d_in[1];
    const float* b0 = (const float*)d_in[2];
    const float* W1 = (const float*)d_in[3];
    const float* b1 = (const float*)d_in[4];
    const float* W2 = (const float*)d_in[5];
    const float* b2 = (const float*)d_in[6];
    float* out = (float*)d_out;
    (void)in_sizes; (void)n_in; (void)out_size;

    cudaFuncSetAttribute(mma_gemm<1>, cudaFuncAttributeMaxDynamicSharedMemorySize, DYN_SMEM);
    cudaFuncSetAttribute(mma_gemm<2>, cudaFuncAttributeMaxDynamicSharedMemorySize, DYN_SMEM);
    cudaFuncSetAttribute(mma_gemm<3>, cudaFuncAttributeMaxDynamicSharedMemorySize, DYN_SMEM);

    wconv_kernel<0><<<(Hh * Cc + 255) / 256, 256>>>(W0, Hh, Cc, Hh);
    wconv_kernel<1><<<(Hh * Hh + 255) / 256, 256>>>(W1, Hh, Hh, Hh);
    wconv_kernel<2><<<(Op * Hh + 255) / 256, 256>>>(W2, Oo, Hh, Op);
    xcvt_kernel<<<(int)(((size_t)Bb * Cc * Nn / 8 + 255) / 256), 256>>>(x);
    mask_kernel<<<dim3((Nn + 255) / 256, Bb), 256>>>(x);
    coef_kernel<<<1, 32>>>();

    mma_gemm<1><<<dim3(NTILE, 1, Bb), 512, DYN_SMEM>>>(b0);
    mma_gemm<2><<<dim3(NTILE, 1, Bb), 512, DYN_SMEM>>>(b1);
    mma_gemm<3><<<dim3(NTILE, Op / 256, Bb), 512, DYN_SMEM>>>(b2);

    topk_kernel<<<Bb * Oo, 256>>>(out);
}

// round 7
// speedup vs baseline: 3.6320x; 1.1307x over previous
#include <cuda_runtime.h>
#include <cuda_fp16.h>
#include <stdint.h>

#define Bb 8
#define Cc 2048
#define Nn 8000
#define Hh 256
#define Oo 1000
#define Op 1024
#define NTILE 63
#define STAGE_A 20480            // 256 rows x 80B (32 f16 + 16B pad)
#define STAGE_B 8704             // 32 k-rows x 272B (128 f16 + 16B pad)
#define STAGE_BYTES (STAGE_A + STAGE_B)
#define NSTAGE 3
#define DYN_SMEM (NSTAGE * STAGE_BYTES)

__device__ __align__(16) __half g_W0h[Hh * Cc];
__device__ __align__(16) __half g_W1h[Hh * Hh];
__device__ __align__(16) __half g_W2h[Op * Hh];
__device__ __align__(16) __half g_xh[(size_t)Bb * Cc * Nn];
__device__ __align__(16) __half g_h0[(size_t)Bb * Hh * Nn];
__device__ __align__(16) __half g_h1[(size_t)Bb * Hh * Nn];
__device__ __align__(16) float  g_y [(size_t)Bb * Oo * Nn];
__device__ unsigned g_nmax[Bb * Nn];
__device__ float g_mask[Bb * Nn];
__device__ float g_coef[Bb * 128];

__device__ __forceinline__ uint32_t smem_u32(const void* p) {
    uint32_t a;
    asm("{ .reg .u64 t; cvta.to.shared.u64 t, %1; cvt.u32.u64 %0, t; }" : "=r"(a) : "l"(p));
    return a;
}
__device__ __forceinline__ void cp16(uint32_t dst, const void* src, int bytes) {
    asm volatile("cp.async.cg.shared.global [%0], [%1], 16, %2;\n"
                 :: "r"(dst), "l"(src), "r"(bytes) : "memory");
}
#define CP_COMMIT() asm volatile("cp.async.commit_group;\n" ::: "memory")
#define CP_WAIT0()  asm volatile("cp.async.wait_group 0;\n" ::: "memory")
#define CP_WAIT1()  asm volatile("cp.async.wait_group 1;\n" ::: "memory")

__device__ __forceinline__ void ldm_x4(uint32_t* r, const void* p) {
    uint32_t a = (uint32_t)__cvta_generic_to_shared(p);
    asm volatile("ldmatrix.sync.aligned.m8n8.x4.shared.b16 {%0,%1,%2,%3}, [%4];\n"
                 : "=r"(r[0]), "=r"(r[1]), "=r"(r[2]), "=r"(r[3]) : "r"(a));
}
__device__ __forceinline__ void ldm_x4t(uint32_t* r, const void* p) {
    uint32_t a = (uint32_t)__cvta_generic_to_shared(p);
    asm volatile("ldmatrix.sync.aligned.m8n8.x4.trans.shared.b16 {%0,%1,%2,%3}, [%4];\n"
                 : "=r"(r[0]), "=r"(r[1]), "=r"(r[2]), "=r"(r[3]) : "r"(a));
}
__device__ __forceinline__ void mma16816(float* d, const uint32_t* a, uint32_t b0, uint32_t b1) {
    asm volatile("mma.sync.aligned.m16n8k16.row.col.f32.f16.f16.f32 "
                 "{%0,%1,%2,%3}, {%4,%5,%6,%7}, {%8,%9}, {%0,%1,%2,%3};\n"
                 : "+f"(d[0]), "+f"(d[1]), "+f"(d[2]), "+f"(d[3])
                 : "r"(a[0]), "r"(a[1]), "r"(a[2]), "r"(a[3]), "r"(b0), "r"(b1));
}
__device__ __forceinline__ uint32_t h2u(__half2 h) { return *reinterpret_cast<uint32_t*>(&h); }

// ---------------------------------------------------------------------------
// C[o(256), n(128)] = W[o][K] x B[k][n], fp16 in, fp32 accum.
// 3-stage cp.async pipeline. L=1: g_xh -> h0 (relu/clamp fp16).
// L=2: h0 -> h1. L=3: -> y fp32 * mask + bias (o-chunks of 256).
// ---------------------------------------------------------------------------
template <int L>
__global__ __launch_bounds__(512, 1) void mma_gemm(const float* __restrict__ bias) {
    constexpr int K = (L == 1) ? Cc : Hh;
    constexpr int NIT = K / 32;
    extern __shared__ __align__(16) char dyn[];
    const uint32_t sm0 = smem_u32(dyn);

    const int tid = threadIdx.x, lane = tid & 31, warp = tid >> 5;
    const int wm = warp >> 2, wn = warp & 3;
    const int b = blockIdx.z, n0 = blockIdx.x * 128, o0 = blockIdx.y * 256;

    const __half* Wh = (L == 1) ? g_W0h : (L == 2) ? g_W1h : g_W2h;
    const __half* Bsrc = ((L == 1) ? g_xh : (L == 2) ? g_h0 : g_h1)
                         + (size_t)b * ((L == 1) ? Cc : Hh) * Nn;

    const int ar0 = tid >> 2, aseg = tid & 3;    // A: rows ar0, ar0+128; 16B segs
    const int br = tid >> 4, bseg = tid & 15;    // B: k-row, 16B n-seg
    const int bn = n0 + bseg * 8;
    const int bnc = (bn < Nn) ? bn : 0;          // clamped src (0-byte cp if OOB)

    auto load_stage = [&](int st, int kk) {
        const uint32_t sa = sm0 + st * STAGE_BYTES;
        const int k0 = kk * 32;
        cp16(sa + ar0 * 80 + aseg * 16, Wh + (size_t)(o0 + ar0) * K + k0 + aseg * 8, 16);
        cp16(sa + (ar0 + 128) * 80 + aseg * 16,
             Wh + (size_t)(o0 + ar0 + 128) * K + k0 + aseg * 8, 16);
        cp16(sa + STAGE_A + br * 272 + bseg * 16,
             Bsrc + (size_t)(k0 + br) * Nn + bnc, (bn < Nn) ? 16 : 0);
        CP_COMMIT();
    };

    float d[4][4][4];
#pragma unroll
    for (int i = 0; i < 4; ++i)
#pragma unroll
        for (int j = 0; j < 4; ++j) { d[i][j][0]=0.f; d[i][j][1]=0.f; d[i][j][2]=0.f; d[i][j][3]=0.f; }

    load_stage(0, 0);
    if (NIT > 1) load_stage(1, 1);
    CP_WAIT1();
    __syncthreads();

#pragma unroll 1
    for (int k = 0; k < NIT; ++k) {
        const int st = k % NSTAGE;
        if (k + 2 < NIT) load_stage((k + 2) % NSTAGE, k + 2);
        {
            char* sa = dyn + st * STAGE_BYTES;
            char* aB = sa + (wm * 64 + (lane & 15)) * 80 + ((lane >> 4) << 4);
            char* bB = sa + STAGE_A + (((lane >> 3) & 1) * 8 + (lane & 7)) * 272
                     + (wn * 32 + ((lane >> 4) << 3)) * 2;
#pragma unroll
            for (int s = 0; s < 2; ++s) {
                uint32_t a[4][4];
#pragma unroll
                for (int mf = 0; mf < 4; ++mf) ldm_x4(a[mf], aB + mf * 16 * 80 + s * 32);
#pragma unroll
                for (int nf2 = 0; nf2 < 2; ++nf2) {
                    uint32_t bq[4];
                    ldm_x4t(bq, bB + s * 16 * 272 + nf2 * 32);
#pragma unroll
                    for (int mf = 0; mf < 4; ++mf) {
                        mma16816(d[mf][nf2 * 2],     a[mf], bq[0], bq[1]);
                        mma16816(d[mf][nf2 * 2 + 1], a[mf], bq[2], bq[3]);
                    }
                }
            }
        }
        if (k + 2 < NIT)      { CP_WAIT1(); }   // stage k+1 complete (k+2 in flight)
        else if (k + 1 < NIT) { CP_WAIT0(); }   // last stage complete
        __syncthreads();
    }

    if (L <= 2) {
        __half* hout = ((L == 1) ? g_h0 : g_h1) + (size_t)b * Hh * Nn;
#pragma unroll
        for (int mf = 0; mf < 4; ++mf) {
            int o = wm * 64 + mf * 16 + (lane >> 2);
            float bs0 = bias[o], bs1 = bias[o + 8];
#pragma unroll
            for (int nf = 0; nf < 4; ++nf) {
                int n = n0 + wn * 32 + nf * 8 + (lane & 3) * 2;
                if (n < Nn) {
                    float v0 = fminf(fmaxf(d[mf][nf][0] + bs0, 0.f), 1e4f);
                    float v1 = fminf(fmaxf(d[mf][nf][1] + bs0, 0.f), 1e4f);
                    float v2 = fminf(fmaxf(d[mf][nf][2] + bs1, 0.f), 1e4f);
                    float v3 = fminf(fmaxf(d[mf][nf][3] + bs1, 0.f), 1e4f);
                    *(uint32_t*)(hout + (size_t)o * Nn + n)       = h2u(__floats2half2_rn(v0, v1));
                    *(uint32_t*)(hout + (size_t)(o + 8) * Nn + n) = h2u(__floats2half2_rn(v2, v3));
                }
            }
        }
    } else {
        float* yp = g_y + (size_t)b * Oo * Nn;
#pragma unroll
        for (int mf = 0; mf < 4; ++mf) {
            int o = o0 + wm * 64 + mf * 16 + (lane >> 2);
#pragma unroll
            for (int nf = 0; nf < 4; ++nf) {
                int n = n0 + wn * 32 + nf * 8 + (lane & 3) * 2;
                if (n < Nn) {
                    float mk0 = g_mask[b * Nn + n], mk1 = g_mask[b * Nn + n + 1];
                    if (o < Oo) {
                        float bs = bias[o];
                        *(float2*)(yp + (size_t)o * Nn + n) =
                            make_float2((d[mf][nf][0] + bs) * mk0, (d[mf][nf][1] + bs) * mk1);
                    }
                    if (o + 8 < Oo) {
                        float bs = bias[o + 8];
                        *(float2*)(yp + (size_t)(o + 8) * Nn + n) =
                            make_float2((d[mf][nf][2] + bs) * mk0, (d[mf][nf][3] + bs) * mk1);
                    }
                }
            }
        }
    }
}

// ---------------------------------------------------------------------------
// Fused x fp32->fp16 + per-n running max over this block's c-chunk.
// grid (16, Bb, 4): 512 n per block (128 thr x float4), c-chunk of 512.
// ---------------------------------------------------------------------------
__global__ __launch_bounds__(128) void xcvt_mask_kernel(const float* __restrict__ x) {
    const int n = blockIdx.x * 512 + threadIdx.x * 4;
    const int b = blockIdx.y;
    const int c0 = blockIdx.z * 512;
    if (n >= Nn) return;
    const float* xp = x + ((size_t)b * Cc + c0) * Nn + n;
    __half* op = g_xh + ((size_t)b * Cc + c0) * Nn + n;
    float4 mx = make_float4(-3.4e38f, -3.4e38f, -3.4e38f, -3.4e38f);
#pragma unroll 4
    for (int c = 0; c < 512; ++c) {
        float4 v = *(const float4*)(xp + (size_t)c * Nn);
        mx.x = fmaxf(mx.x, v.x); mx.y = fmaxf(mx.y, v.y);
        mx.z = fmaxf(mx.z, v.z); mx.w = fmaxf(mx.w, v.w);
        uint2 o;
        o.x = h2u(__floats2half2_rn(v.x, v.y));
        o.y = h2u(__floats2half2_rn(v.z, v.w));
        *(uint2*)(op + (size_t)c * Nn) = o;
    }
    float m4[4] = {mx.x, mx.y, mx.z, mx.w};
#pragma unroll
    for (int j = 0; j < 4; ++j) {
        unsigned u = __float_as_uint(m4[j]);
        u = (u & 0x80000000u) ? ~u : (u | 0x80000000u);
        atomicMax(&g_nmax[b * Nn + n + j], u);
    }
}

__global__ void mask2_kernel() {
    int i = blockIdx.x * 256 + threadIdx.x;
    if (i < Bb * Nn) g_mask[i] = (g_nmax[i] > 0x80000000u) ? 1.f : 0.f;
}

template <int WSEL>
__global__ void wconv_kernel(const float* __restrict__ W, int rows, int cols, int orows) {
    __half* outp = (WSEL == 0) ? g_W0h : (WSEL == 1) ? g_W1h : g_W2h;
    int i = blockIdx.x * 256 + threadIdx.x;
    if (i >= orows * cols) return;
    int r = i / cols, c = i - r * cols;
    outp[(size_t)r * cols + c] = __float2half_rn((r < rows) ? W[(size_t)r * cols + c] : 0.f);
}

__global__ void coef_kernel() {
    int b = threadIdx.x;
    if (b >= Bb) return;
    float s = 0.f, d10 = 0.f, d25 = 0.f, d50 = 0.f;
    for (int j = 0; j < 100; ++j) {
        s += g_mask[b * Nn + j];
        if (j == 9)  d10 = s;
        if (j == 24) d25 = s;
        if (j == 49) d50 = s;
    }
    float d100 = s;
    for (int j = 0; j < 100; ++j) {
        float w = 0.25f / d100;
        if (j < 50) w += 0.25f / d50;
        if (j < 25) w += 0.25f / d25;
        if (j < 10) w += 0.25f / d10;
        g_coef[b * 128 + j] = g_mask[b * Nn + j] * w;
    }
}

__global__ __launch_bounds__(256) void topk_kernel(float* __restrict__ out) {
    const int row = blockIdx.x, b = row / Oo, tid = threadIdx.x;
    __shared__ uint32_t su[Nn];
    __shared__ uint32_t hist[256];
    __shared__ uint32_t s_sel[2];
    __shared__ uint32_t s_cnt;
    __shared__ uint32_t buf[128];
    __shared__ uint32_t srt[128];
    __shared__ float partial[256];

    const float* yp = g_y + (size_t)row * Nn;
    for (int i = tid; i < Nn; i += 256) {
        uint32_t bits = __float_as_uint(yp[i]);
        su[i] = (bits & 0x80000000u) ? ~bits : (bits | 0x80000000u);
    }
    uint32_t prefix = 0, hiMask = 0;
    int K = 100;
    for (int level = 3; level >= 0; --level) {
        const int shift = level * 8;
        hist[tid] = 0;
        __syncthreads();
        for (int i = tid; i < Nn; i += 256) {
            uint32_t v = su[i];
            if ((v & hiMask) == prefix) atomicAdd(&hist[(v >> shift) & 255u], 1u);
        }
        __syncthreads();
        if (tid == 0) {
            int cum = 0, bin = 255;
            for (; bin > 0; --bin) {
                int c = (int)hist[bin];
                if (cum + c >= K) break;
                cum += c;
            }
            s_sel[0] = (uint32_t)bin; s_sel[1] = (uint32_t)(K - cum);
        }
        __syncthreads();
        prefix |= (s_sel[0] << shift);
        K = (int)s_sel[1];
        hiMask |= (0xFFu << shift);
        __syncthreads();
    }
    const uint32_t thr = prefix;
    if (tid == 0) s_cnt = 0;
    __syncthreads();
    for (int i = tid; i < Nn; i += 256) {
        uint32_t v = su[i];
        if (v > thr) {
            uint32_t idx = atomicAdd(&s_cnt, 1u);
            if (idx < 128u) buf[idx] = v;
        }
    }
    __syncthreads();
    int g = (int)min(s_cnt, 100u);
    for (int j = g + tid; j < 100; j += 256) buf[j] = thr;
    __syncthreads();
    if (tid < 100) {
        uint32_t v = buf[tid];
        int rank = 0;
#pragma unroll 4
        for (int j = 0; j < 100; ++j) {
            uint32_t w = buf[j];
            rank += (w > v) || (w == v && j < tid);
        }
        srt[rank] = v;
    }
    __syncthreads();
    float t = 0.f;
    if (tid < 100) {
        uint32_t u = srt[tid];
        uint32_t bits = (u & 0x80000000u) ? (u & 0x7FFFFFFFu) : ~u;
        t = __uint_as_float(bits) * g_coef[b * 128 + tid];
    }
    partial[tid] = t;
    __syncthreads();
    for (int s = 128; s > 0; s >>= 1) {
        if (tid < s) partial[tid] += partial[tid + s];
        __syncthreads();
    }
    if (tid == 0) out[row] = partial[0];
}

extern "C" void kernel_launch(void* const* d_in, const int* in_sizes, int n_in,
                              void* d_out, int out_size) {
    const float* x  = (const float*)d_in[0];
    const float* W0 = (const float*)d_in[1];
    const float* b0 = (const float*)d_in[2];
    const float* W1 = (const float*)d_in[3];
    const float* b1 = (const float*)d_in[4];
    const float* W2 = (const float*)d_in[5];
    const float* b2 = (const float*)d_in[6];
    float* out = (float*)d_out;
    (void)in_sizes; (void)n_in; (void)out_size;

    cudaFuncSetAttribute(mma_gemm<1>, cudaFuncAttributeMaxDynamicSharedMemorySize, DYN_SMEM);
    cudaFuncSetAttribute(mma_gemm<2>, cudaFuncAttributeMaxDynamicSharedMemorySize, DYN_SMEM);
    cudaFuncSetAttribute(mma_gemm<3>, cudaFuncAttributeMaxDynamicSharedMemorySize, DYN_SMEM);

    void* nmax_ptr = nullptr;
    cudaGetSymbolAddress(&nmax_ptr, g_nmax);
    cudaMemsetAsync(nmax_ptr, 0, sizeof(unsigned) * Bb * Nn);

    wconv_kernel<0><<<(Hh * Cc + 255) / 256, 256>>>(W0, Hh, Cc, Hh);
    wconv_kernel<1><<<(Hh * Hh + 255) / 256, 256>>>(W1, Hh, Hh, Hh);
    wconv_kernel<2><<<(Op * Hh + 255) / 256, 256>>>(W2, Oo, Hh, Op);
    xcvt_mask_kernel<<<dim3(16, Bb, 4), 128>>>(x);
    mask2_kernel<<<(Bb * Nn + 255) / 256, 256>>>();
    coef_kernel<<<1, 32>>>();

    mma_gemm<1><<<dim3(NTILE, 1, Bb), 512, DYN_SMEM>>>(b0);
    mma_gemm<2><<<dim3(NTILE, 1, Bb), 512, DYN_SMEM>>>(b1);
    mma_gemm<3><<<dim3(NTILE, Op / 256, Bb), 512, DYN_SMEM>>>(b2);

    topk_kernel<<<Bb * Oo, 256>>>(out);
}

// round 8
// speedup vs baseline: 4.2454x; 1.1689x over previous
#include <cuda_runtime.h>
#include <cuda_fp16.h>
#include <stdint.h>

#define Bb 8
#define Cc 2048
#define Nn 8000
#define Hh 256
#define Oo 1000
#define Op 1024
#define NTILE 63
#define STAGE_A 20480            // 256 rows x 80B (32 f16 + 16B pad)
#define STAGE_B 8704             // 32 k-rows x 272B (128 f16 + 16B pad)
#define STAGE_BYTES (STAGE_A + STAGE_B)
#define NSTAGE 3
#define DYN_SMEM (NSTAGE * STAGE_BYTES)

__device__ __align__(16) __half g_W0h[Hh * Cc];
__device__ __align__(16) __half g_W1h[Hh * Hh];
__device__ __align__(16) __half g_W2h[Op * Hh];
__device__ __align__(16) __half g_h0[(size_t)Bb * Hh * Nn];
__device__ __align__(16) __half g_h1[(size_t)Bb * Hh * Nn];
__device__ __align__(16) float  g_y [(size_t)Bb * Oo * Nn];
__device__ float g_mask[Bb * Nn];
__device__ float g_coef[Bb * 128];

__device__ __forceinline__ uint32_t smem_u32(const void* p) {
    uint32_t a;
    asm("{ .reg .u64 t; cvta.to.shared.u64 t, %1; cvt.u32.u64 %0, t; }" : "=r"(a) : "l"(p));
    return a;
}
__device__ __forceinline__ void cp16(uint32_t dst, const void* src, int bytes) {
    asm volatile("cp.async.cg.shared.global [%0], [%1], 16, %2;\n"
                 :: "r"(dst), "l"(src), "r"(bytes) : "memory");
}
#define CP_COMMIT() asm volatile("cp.async.commit_group;\n" ::: "memory")
#define CP_WAIT0()  asm volatile("cp.async.wait_group 0;\n" ::: "memory")
#define CP_WAIT1()  asm volatile("cp.async.wait_group 1;\n" ::: "memory")

__device__ __forceinline__ void ldm_x4(uint32_t* r, const void* p) {
    uint32_t a = (uint32_t)__cvta_generic_to_shared(p);
    asm volatile("ldmatrix.sync.aligned.m8n8.x4.shared.b16 {%0,%1,%2,%3}, [%4];\n"
                 : "=r"(r[0]), "=r"(r[1]), "=r"(r[2]), "=r"(r[3]) : "r"(a));
}
__device__ __forceinline__ void ldm_x4t(uint32_t* r, const void* p) {
    uint32_t a = (uint32_t)__cvta_generic_to_shared(p);
    asm volatile("ldmatrix.sync.aligned.m8n8.x4.trans.shared.b16 {%0,%1,%2,%3}, [%4];\n"
                 : "=r"(r[0]), "=r"(r[1]), "=r"(r[2]), "=r"(r[3]) : "r"(a));
}
__device__ __forceinline__ void mma16816(float* d, const uint32_t* a, uint32_t b0, uint32_t b1) {
    asm volatile("mma.sync.aligned.m16n8k16.row.col.f32.f16.f16.f32 "
                 "{%0,%1,%2,%3}, {%4,%5,%6,%7}, {%8,%9}, {%0,%1,%2,%3};\n"
                 : "+f"(d[0]), "+f"(d[1]), "+f"(d[2]), "+f"(d[3])
                 : "r"(a[0]), "r"(a[1]), "r"(a[2]), "r"(a[3]), "r"(b0), "r"(b1));
}
__device__ __forceinline__ uint32_t h2u(__half2 h) { return *reinterpret_cast<uint32_t*>(&h); }

// ---------------------------------------------------------------------------
// C[o(256), n(128)] = W[o][K] x B[k][n], fp16 in, fp32 accum.
// W via 3-stage cp.async. L=1: B from x fp32, converted fp32->fp16 in registers
//   (LDG -> cvt+hmax -> STS double-buffer); writes h0 + g_mask.
// L=2: B=g_h0 via cp.async -> h1. L=3: B=g_h1 -> y fp32 * mask + bias.
// ---------------------------------------------------------------------------
template <int L>
__global__ __launch_bounds__(512, 1) void mma_gemm(const float* __restrict__ x,
                                                   const float* __restrict__ bias) {
    constexpr int K = (L == 1) ? Cc : Hh;
    constexpr int NIT = K / 32;
    extern __shared__ __align__(16) char dyn[];
    const uint32_t sm0 = smem_u32(dyn);
    __shared__ int s_any[128];

    const int tid = threadIdx.x, lane = tid & 31, warp = tid >> 5;
    const int wm = warp >> 2, wn = warp & 3;
    const int b = blockIdx.z, n0 = blockIdx.x * 128, o0 = blockIdx.y * 256;

    const __half* Wh = (L == 1) ? g_W0h : (L == 2) ? g_W1h : g_W2h;
    const __half* Bsrc = ((L == 2) ? g_h0 : g_h1) + (size_t)b * Hh * Nn;  // L>=2
    const float*  xb   = x + (size_t)b * Cc * Nn;                          // L==1

    const int ar0 = tid >> 2, aseg = tid & 3;    // A: rows ar0, ar0+128; 16B segs
    const int br = tid >> 4, bseg = tid & 15;    // B: k-row, 16B n-seg
    const int bn = n0 + bseg * 8;
    const int bnc = (bn < Nn) ? bn : 0;

    auto load_stage = [&](int st, int kk) {
        const uint32_t sa = sm0 + st * STAGE_BYTES;
        const int k0 = kk * 32;
        cp16(sa + ar0 * 80 + aseg * 16, Wh + (size_t)(o0 + ar0) * K + k0 + aseg * 8, 16);
        cp16(sa + (ar0 + 128) * 80 + aseg * 16,
             Wh + (size_t)(o0 + ar0 + 128) * K + k0 + aseg * 8, 16);
        if (L >= 2)
            cp16(sa + STAGE_A + br * 272 + bseg * 16,
                 Bsrc + (size_t)(k0 + br) * Nn + bnc, (bn < Nn) ? 16 : 0);
        CP_COMMIT();
    };

    // L==1 B register pipeline: LDG fp32 -> cvt fp16 + running max -> STS
    float4 rb0, rb1;
    __half2 hm[4];
    if (L == 1) {
#pragma unroll
        for (int j = 0; j < 4; ++j) hm[j] = __floats2half2_rn(0.f, 0.f);
        if (tid < 128) s_any[tid] = 0;
    }
    auto ldgB = [&](int kk, float4& a, float4& c) {
        if (bn < Nn) {
            const float* p = xb + (size_t)(kk * 32 + br) * Nn + bn;
            a = *(const float4*)p; c = *(const float4*)(p + 4);
        } else { a = make_float4(0.f, 0.f, 0.f, 0.f); c = a; }
    };
    auto stsB = [&](int st, const float4& a, const float4& c) {
        __half2 h0 = __floats2half2_rn(a.x, a.y), h1 = __floats2half2_rn(a.z, a.w);
        __half2 h2 = __floats2half2_rn(c.x, c.y), h3 = __floats2half2_rn(c.z, c.w);
        hm[0] = __hmax2(hm[0], h0); hm[1] = __hmax2(hm[1], h1);
        hm[2] = __hmax2(hm[2], h2); hm[3] = __hmax2(hm[3], h3);
        uint32_t dst = sm0 + st * STAGE_BYTES + STAGE_A + br * 272 + bseg * 16;
        asm volatile("st.shared.v4.b32 [%0], {%1,%2,%3,%4};\n"
                     :: "r"(dst), "r"(h2u(h0)), "r"(h2u(h1)), "r"(h2u(h2)), "r"(h2u(h3))
                     : "memory");
    };

    float d[4][4][4];
#pragma unroll
    for (int i = 0; i < 4; ++i)
#pragma unroll
        for (int j = 0; j < 4; ++j) { d[i][j][0]=0.f; d[i][j][1]=0.f; d[i][j][2]=0.f; d[i][j][3]=0.f; }

    load_stage(0, 0);
    if (NIT > 1) load_stage(1, 1);
    if (L == 1) {
        float4 a, c;
        ldgB(0, a, c); stsB(0, a, c);
        if (NIT > 1) ldgB(1, rb0, rb1);
    }
    CP_WAIT1();
    __syncthreads();

#pragma unroll 1
    for (int k = 0; k < NIT; ++k) {
        const int st = k % NSTAGE;
        if (k + 2 < NIT) load_stage((k + 2) % NSTAGE, k + 2);
        if (L == 1) {
            if (k + 1 < NIT) stsB((k + 1) % NSTAGE, rb0, rb1);
            if (k + 2 < NIT) ldgB(k + 2, rb0, rb1);
        }
        {
            char* sa = dyn + st * STAGE_BYTES;
            char* aB = sa + (wm * 64 + (lane & 15)) * 80 + ((lane >> 4) << 4);
            char* bB = sa + STAGE_A + (((lane >> 3) & 1) * 8 + (lane & 7)) * 272
                     + (wn * 32 + ((lane >> 4) << 3)) * 2;
#pragma unroll
            for (int s = 0; s < 2; ++s) {
                uint32_t a[4][4];
#pragma unroll
                for (int mf = 0; mf < 4; ++mf) ldm_x4(a[mf], aB + mf * 16 * 80 + s * 32);
#pragma unroll
                for (int nf2 = 0; nf2 < 2; ++nf2) {
                    uint32_t bq[4];
                    ldm_x4t(bq, bB + s * 16 * 272 + nf2 * 32);
#pragma unroll
                    for (int mf = 0; mf < 4; ++mf) {
                        mma16816(d[mf][nf2 * 2],     a[mf], bq[0], bq[1]);
                        mma16816(d[mf][nf2 * 2 + 1], a[mf], bq[2], bq[3]);
                    }
                }
            }
        }
        if (k + 2 < NIT)      { CP_WAIT1(); }
        else if (k + 1 < NIT) { CP_WAIT0(); }
        __syncthreads();
    }

    if (L <= 2) {
        __half* hout = ((L == 1) ? g_h0 : g_h1) + (size_t)b * Hh * Nn;
#pragma unroll
        for (int mf = 0; mf < 4; ++mf) {
            int o = wm * 64 + mf * 16 + (lane >> 2);
            float bs0 = bias[o], bs1 = bias[o + 8];
#pragma unroll
            for (int nf = 0; nf < 4; ++nf) {
                int n = n0 + wn * 32 + nf * 8 + (lane & 3) * 2;
                if (n < Nn) {
                    float v0 = fminf(fmaxf(d[mf][nf][0] + bs0, 0.f), 1e4f);
                    float v1 = fminf(fmaxf(d[mf][nf][1] + bs0, 0.f), 1e4f);
                    float v2 = fminf(fmaxf(d[mf][nf][2] + bs1, 0.f), 1e4f);
                    float v3 = fminf(fmaxf(d[mf][nf][3] + bs1, 0.f), 1e4f);
                    *(uint32_t*)(hout + (size_t)o * Nn + n)       = h2u(__floats2half2_rn(v0, v1));
                    *(uint32_t*)(hout + (size_t)(o + 8) * Nn + n) = h2u(__floats2half2_rn(v2, v3));
                }
            }
        }
        if (L == 1) {   // mask from the in-flight fp16 max
            __syncthreads();
#pragma unroll
            for (int j = 0; j < 4; ++j) {
                if (__low2float(hm[j])  > 0.f) atomicOr(&s_any[bseg * 8 + 2 * j],     1);
                if (__high2float(hm[j]) > 0.f) atomicOr(&s_any[bseg * 8 + 2 * j + 1], 1);
            }
            __syncthreads();
            if (tid < 128 && n0 + tid < Nn)
                g_mask[b * Nn + n0 + tid] = s_any[tid] ? 1.f : 0.f;
        }
    } else {
        float* yp = g_y + (size_t)b * Oo * Nn;
#pragma unroll
        for (int mf = 0; mf < 4; ++mf) {
            int o = o0 + wm * 64 + mf * 16 + (lane >> 2);
#pragma unroll
            for (int nf = 0; nf < 4; ++nf) {
                int n = n0 + wn * 32 + nf * 8 + (lane & 3) * 2;
                if (n < Nn) {
                    float mk0 = g_mask[b * Nn + n], mk1 = g_mask[b * Nn + n + 1];
                    if (o < Oo) {
                        float bs = bias[o];
                        *(float2*)(yp + (size_t)o * Nn + n) =
                            make_float2((d[mf][nf][0] + bs) * mk0, (d[mf][nf][1] + bs) * mk1);
                    }
                    if (o + 8 < Oo) {
                        float bs = bias[o + 8];
                        *(float2*)(yp + (size_t)(o + 8) * Nn + n) =
                            make_float2((d[mf][nf][2] + bs) * mk0, (d[mf][nf][3] + bs) * mk1);
                    }
                }
            }
        }
    }
}

template <int WSEL>
__global__ void wconv_kernel(const float* __restrict__ W, int rows, int cols, int orows) {
    __half* outp = (WSEL == 0) ? g_W0h : (WSEL == 1) ? g_W1h : g_W2h;
    int i = blockIdx.x * 256 + threadIdx.x;
    if (i >= orows * cols) return;
    int r = i / cols, c = i - r * cols;
    outp[(size_t)r * cols + c] = __float2half_rn((r < rows) ? W[(size_t)r * cols + c] : 0.f);
}

__global__ void coef_kernel() {
    int b = threadIdx.x;
    if (b >= Bb) return;
    float s = 0.f, d10 = 0.f, d25 = 0.f, d50 = 0.f;
    for (int j = 0; j < 100; ++j) {
        s += g_mask[b * Nn + j];
        if (j == 9)  d10 = s;
        if (j == 24) d25 = s;
        if (j == 49) d50 = s;
    }
    float d100 = s;
    for (int j = 0; j < 100; ++j) {
        float w = 0.25f / d100;
        if (j < 50) w += 0.25f / d50;
        if (j < 25) w += 0.25f / d25;
        if (j < 10) w += 0.25f / d10;
        g_coef[b * 128 + j] = g_mask[b * Nn + j] * w;
    }
}

__global__ __launch_bounds__(256) void topk_kernel(float* __restrict__ out) {
    const int row = blockIdx.x, b = row / Oo, tid = threadIdx.x;
    __shared__ uint32_t su[Nn];
    __shared__ uint32_t hist[256];
    __shared__ uint32_t s_sel[2];
    __shared__ uint32_t s_cnt;
    __shared__ uint32_t buf[128];
    __shared__ uint32_t srt[128];
    __shared__ float partial[256];

    const float* yp = g_y + (size_t)row * Nn;
    for (int i = tid; i < Nn; i += 256) {
        uint32_t bits = __float_as_uint(yp[i]);
        su[i] = (bits & 0x80000000u) ? ~bits : (bits | 0x80000000u);
    }
    uint32_t prefix = 0, hiMask = 0;
    int K = 100;
    for (int level = 3; level >= 0; --level) {
        const int shift = level * 8;
        hist[tid] = 0;
        __syncthreads();
        for (int i = tid; i < Nn; i += 256) {
            uint32_t v = su[i];
            if ((v & hiMask) == prefix) atomicAdd(&hist[(v >> shift) & 255u], 1u);
        }
        __syncthreads();
        if (tid == 0) {
            int cum = 0, bin = 255;
            for (; bin > 0; --bin) {
                int c = (int)hist[bin];
                if (cum + c >= K) break;
                cum += c;
            }
            s_sel[0] = (uint32_t)bin; s_sel[1] = (uint32_t)(K - cum);
        }
        __syncthreads();
        prefix |= (s_sel[0] << shift);
        K = (int)s_sel[1];
        hiMask |= (0xFFu << shift);
        __syncthreads();
    }
    const uint32_t thr = prefix;
    if (tid == 0) s_cnt = 0;
    __syncthreads();
    for (int i = tid; i < Nn; i += 256) {
        uint32_t v = su[i];
        if (v > thr) {
            uint32_t idx = atomicAdd(&s_cnt, 1u);
            if (idx < 128u) buf[idx] = v;
        }
    }
    __syncthreads();
    int g = (int)min(s_cnt, 100u);
    for (int j = g + tid; j < 100; j += 256) buf[j] = thr;
    __syncthreads();
    if (tid < 100) {
        uint32_t v = buf[tid];
        int rank = 0;
#pragma unroll 4
        for (int j = 0; j < 100; ++j) {
            uint32_t w = buf[j];
            rank += (w > v) || (w == v && j < tid);
        }
        srt[rank] = v;
    }
    __syncthreads();
    float t = 0.f;
    if (tid < 100) {
        uint32_t u = srt[tid];
        uint32_t bits = (u & 0x80000000u) ? (u & 0x7FFFFFFFu) : ~u;
        t = __uint_as_float(bits) * g_coef[b * 128 + tid];
    }
    partial[tid] = t;
    __syncthreads();
    for (int s = 128; s > 0; s >>= 1) {
        if (tid < s) partial[tid] += partial[tid + s];
        __syncthreads();
    }
    if (tid == 0) out[row] = partial[0];
}

extern "C" void kernel_launch(void* const* d_in, const int* in_sizes, int n_in,
                              void* d_out, int out_size) {
    const float* x  = (const float*)d_in[0];
    const float* W0 = (const float*)d_in[1];
    const float* b0 = (const float*)d_in[2];
    const float* W1 = (const float*)d_in[3];
    const float* b1 = (const float*)d_in[4];
    const float* W2 = (const float*)d_in[5];
    const float* b2 = (const float*)d_in[6];
    float* out = (float*)d_out;
    (void)in_sizes; (void)n_in; (void)out_size;

    cudaFuncSetAttribute(mma_gemm<1>, cudaFuncAttributeMaxDynamicSharedMemorySize, DYN_SMEM);
    cudaFuncSetAttribute(mma_gemm<2>, cudaFuncAttributeMaxDynamicSharedMemorySize, DYN_SMEM);
    cudaFuncSetAttribute(mma_gemm<3>, cudaFuncAttributeMaxDynamicSharedMemorySize, DYN_SMEM);

    wconv_kernel<0><<<(Hh * Cc + 255) / 256, 256>>>(W0, Hh, Cc, Hh);
    wconv_kernel<1><<<(Hh * Hh + 255) / 256, 256>>>(W1, Hh, Hh, Hh);
    wconv_kernel<2><<<(Op * Hh + 255) / 256, 256>>>(W2, Oo, Hh, Op);

    mma_gemm<1><<<dim3(NTILE, 1, Bb), 512, DYN_SMEM>>>(x, b0);   // h0 + mask
    coef_kernel<<<1, 32>>>();
    mma_gemm<2><<<dim3(NTILE, 1, Bb), 512, DYN_SMEM>>>(x, b1);   // h1
    mma_gemm<3><<<dim3(NTILE, Op / 256, Bb), 512, DYN_SMEM>>>(x, b2);  // y

    topk_kernel<<<Bb * Oo, 256>>>(out);
}

// round 9
// speedup vs baseline: 4.3581x; 1.0265x over previous
#include <cuda_runtime.h>
#include <cuda_fp16.h>
#include <stdint.h>

#define Bb 8
#define Cc 2048
#define Nn 8000
#define Hh 256
#define Oo 1000
#define Op 1024
#define NTILE 63
#define STAGE_A 20480            // 256 rows x 80B (32 f16 + 16B pad)
#define STAGE_B 8704             // 32 k-rows x 272B (128 f16 + 16B pad)
#define STAGE_BYTES (STAGE_A + STAGE_B)
#define NSTAGE 3
#define SMEM_H0 (NSTAGE * STAGE_BYTES)            // 87552
#define SMEM_H1 (SMEM_H0 + 256 * 272)             // 157184
#define DYN_SMEM (SMEM_H1 + 256 * 272)            // 226816

__device__ __align__(16) __half g_W0h[Hh * Cc];
__device__ __align__(16) __half g_W1h[Hh * Hh];
__device__ __align__(16) __half g_W2h[Op * Hh];
__device__ __align__(16) float  g_y [(size_t)Bb * Oo * Nn];
__device__ float g_mask[Bb * Nn];
__device__ float g_coef[Bb * 128];

__device__ __forceinline__ uint32_t smem_u32(const void* p) {
    uint32_t a;
    asm("{ .reg .u64 t; cvta.to.shared.u64 t, %1; cvt.u32.u64 %0, t; }" : "=r"(a) : "l"(p));
    return a;
}
__device__ __forceinline__ void cp16(uint32_t dst, const void* src, int bytes) {
    asm volatile("cp.async.cg.shared.global [%0], [%1], 16, %2;\n"
                 :: "r"(dst), "l"(src), "r"(bytes) : "memory");
}
#define CP_COMMIT() asm volatile("cp.async.commit_group;\n" ::: "memory")
#define CP_WAIT0()  asm volatile("cp.async.wait_group 0;\n" ::: "memory")
#define CP_WAIT1()  asm volatile("cp.async.wait_group 1;\n" ::: "memory")

__device__ __forceinline__ void ldm_x4(uint32_t* r, const void* p) {
    uint32_t a = (uint32_t)__cvta_generic_to_shared(p);
    asm volatile("ldmatrix.sync.aligned.m8n8.x4.shared.b16 {%0,%1,%2,%3}, [%4];\n"
                 : "=r"(r[0]), "=r"(r[1]), "=r"(r[2]), "=r"(r[3]) : "r"(a));
}
__device__ __forceinline__ void ldm_x4t(uint32_t* r, const void* p) {
    uint32_t a = (uint32_t)__cvta_generic_to_shared(p);
    asm volatile("ldmatrix.sync.aligned.m8n8.x4.trans.shared.b16 {%0,%1,%2,%3}, [%4];\n"
                 : "=r"(r[0]), "=r"(r[1]), "=r"(r[2]), "=r"(r[3]) : "r"(a));
}
__device__ __forceinline__ void mma16816(float* d, const uint32_t* a, uint32_t b0, uint32_t b1) {
    asm volatile("mma.sync.aligned.m16n8k16.row.col.f32.f16.f16.f32 "
                 "{%0,%1,%2,%3}, {%4,%5,%6,%7}, {%8,%9}, {%0,%1,%2,%3};\n"
                 : "+f"(d[0]), "+f"(d[1]), "+f"(d[2]), "+f"(d[3])
                 : "r"(a[0]), "r"(a[1]), "r"(a[2]), "r"(a[3]), "r"(b0), "r"(b1));
}
__device__ __forceinline__ uint32_t h2u(__half2 h) { return *reinterpret_cast<uint32_t*>(&h); }

// one 256x128x32 k-chunk: A from aB (80B pitch), B from bB (272B pitch)
__device__ __forceinline__ void compute_iter(char* aB, char* bB, float d[4][4][4]) {
#pragma unroll
    for (int s = 0; s < 2; ++s) {
        uint32_t a[4][4];
#pragma unroll
        for (int mf = 0; mf < 4; ++mf) ldm_x4(a[mf], aB + mf * 16 * 80 + s * 32);
#pragma unroll
        for (int nf2 = 0; nf2 < 2; ++nf2) {
            uint32_t bq[4];
            ldm_x4t(bq, bB + s * 16 * 272 + nf2 * 32);
#pragma unroll
            for (int mf = 0; mf < 4; ++mf) {
                mma16816(d[mf][nf2 * 2],     a[mf], bq[0], bq[1]);
                mma16816(d[mf][nf2 * 2 + 1], a[mf], bq[2], bq[3]);
            }
        }
    }
}

// ---------------------------------------------------------------------------
// Fused 3-layer MLP per (b, n-tile of 128). h0/h1 stay in smem.
// ---------------------------------------------------------------------------
__global__ __launch_bounds__(512, 1) void fused_mlp(const float* __restrict__ x,
                                                    const float* __restrict__ b0,
                                                    const float* __restrict__ b1,
                                                    const float* __restrict__ b2) {
    extern __shared__ __align__(16) char dyn[];
    const uint32_t sm0 = smem_u32(dyn);
    __shared__ int s_any[128];

    const int tid = threadIdx.x, lane = tid & 31, warp = tid >> 5;
    const int wm = warp >> 2, wn = warp & 3;
    const int b = blockIdx.z, n0 = blockIdx.x * 128;

    const float* xb = x + (size_t)b * Cc * Nn;

    const int ar0 = tid >> 2, aseg = tid & 3;    // A: rows ar0, ar0+128; 16B segs
    const int br = tid >> 4, bseg = tid & 15;    // B: k-row, 16B n-seg
    const int bn = n0 + bseg * 8;

    // lane-fixed fragment offsets
    char* const aLane = dyn + (wm * 64 + (lane & 15)) * 80 + ((lane >> 4) << 4);
    const int   bLane = (((lane >> 3) & 1) * 8 + (lane & 7)) * 272
                      + (wn * 32 + ((lane >> 4) << 3)) * 2;

    auto load_stageA = [&](int st, int kk, const __half* W, int Kd) {
        const uint32_t sa = sm0 + st * STAGE_BYTES;
        const int k0 = kk * 32;
        cp16(sa + ar0 * 80 + aseg * 16, W + (size_t)ar0 * Kd + k0 + aseg * 8, 16);
        cp16(sa + (ar0 + 128) * 80 + aseg * 16,
             W + (size_t)(ar0 + 128) * Kd + k0 + aseg * 8, 16);
    };

    // phase-1 B register pipeline: LDG fp32 -> cvt fp16 + running max -> STS
    float4 rb0, rb1;
    __half2 hm[4];
#pragma unroll
    for (int j = 0; j < 4; ++j) hm[j] = __floats2half2_rn(0.f, 0.f);
    if (tid < 128) s_any[tid] = 0;

    auto ldgB = [&](int kk, float4& a, float4& c) {
        if (bn < Nn) {
            const float* p = xb + (size_t)(kk * 32 + br) * Nn + bn;
            a = *(const float4*)p; c = *(const float4*)(p + 4);
        } else { a = make_float4(0.f, 0.f, 0.f, 0.f); c = a; }
    };
    auto stsB = [&](int st, const float4& a, const float4& c) {
        __half2 h0 = __floats2half2_rn(a.x, a.y), h1 = __floats2half2_rn(a.z, a.w);
        __half2 h2 = __floats2half2_rn(c.x, c.y), h3 = __floats2half2_rn(c.z, c.w);
        hm[0] = __hmax2(hm[0], h0); hm[1] = __hmax2(hm[1], h1);
        hm[2] = __hmax2(hm[2], h2); hm[3] = __hmax2(hm[3], h3);
        uint32_t dst = sm0 + st * STAGE_BYTES + STAGE_A + br * 272 + bseg * 16;
        asm volatile("st.shared.v4.b32 [%0], {%1,%2,%3,%4};\n"
                     :: "r"(dst), "r"(h2u(h0)), "r"(h2u(h1)), "r"(h2u(h2)), "r"(h2u(h3))
                     : "memory");
    };

    float d[4][4][4];
    auto zero_acc = [&]() {
#pragma unroll
        for (int i = 0; i < 4; ++i)
#pragma unroll
            for (int j = 0; j < 4; ++j) { d[i][j][0]=0.f; d[i][j][1]=0.f; d[i][j][2]=0.f; d[i][j][3]=0.f; }
    };
    // epilogue -> smem h-tile (relu/clamp, fp16)
    auto epi_smem = [&](char* hs, const float* __restrict__ bias) {
#pragma unroll
        for (int mf = 0; mf < 4; ++mf) {
            int o = wm * 64 + mf * 16 + (lane >> 2);
            float bs0 = bias[o], bs1 = bias[o + 8];
#pragma unroll
            for (int nf = 0; nf < 4; ++nf) {
                int nl = wn * 32 + nf * 8 + (lane & 3) * 2;
                float v0 = fminf(fmaxf(d[mf][nf][0] + bs0, 0.f), 1e4f);
                float v1 = fminf(fmaxf(d[mf][nf][1] + bs0, 0.f), 1e4f);
                float v2 = fminf(fmaxf(d[mf][nf][2] + bs1, 0.f), 1e4f);
                float v3 = fminf(fmaxf(d[mf][nf][3] + bs1, 0.f), 1e4f);
                *(uint32_t*)(hs + o * 272 + nl * 2)       = h2u(__floats2half2_rn(v0, v1));
                *(uint32_t*)(hs + (o + 8) * 272 + nl * 2) = h2u(__floats2half2_rn(v2, v3));
            }
        }
    };

    // ======================= Phase 1: h0 = act(W0 @ x) =======================
    zero_acc();
    {
        constexpr int NIT = Cc / 32;
        load_stageA(0, 0, g_W0h, Cc);
        { float4 a, c; ldgB(0, a, c); stsB(0, a, c); }
        CP_COMMIT();
        load_stageA(1, 1, g_W0h, Cc);
        ldgB(1, rb0, rb1);
        CP_COMMIT();
        CP_WAIT1();
        __syncthreads();
#pragma unroll 1
        for (int k = 0; k < NIT; ++k) {
            const int st = k % NSTAGE;
            if (k + 2 < NIT) { load_stageA((k + 2) % NSTAGE, k + 2, g_W0h, Cc); }
            if (k + 1 < NIT) stsB((k + 1) % NSTAGE, rb0, rb1);
            if (k + 2 < NIT) { ldgB(k + 2, rb0, rb1); CP_COMMIT(); }
            compute_iter(aLane + st * STAGE_BYTES,
                         dyn + st * STAGE_BYTES + STAGE_A + bLane, d);
            if (k + 2 < NIT)      { CP_WAIT1(); }
            else if (k + 1 < NIT) { CP_WAIT0(); }
            __syncthreads();
        }
    }
    epi_smem(dyn + SMEM_H0, b0);
    // mask from in-flight fp16 max (CTA-local; also publish for coef_kernel)
#pragma unroll
    for (int j = 0; j < 4; ++j) {
        if (__low2float(hm[j])  > 0.f) atomicOr(&s_any[bseg * 8 + 2 * j],     1);
        if (__high2float(hm[j]) > 0.f) atomicOr(&s_any[bseg * 8 + 2 * j + 1], 1);
    }
    __syncthreads();
    if (tid < 128 && n0 + tid < Nn)
        g_mask[b * Nn + n0 + tid] = s_any[tid] ? 1.f : 0.f;

    // ======================= Phase 2: h1 = act(W1 @ h0) ======================
    zero_acc();
    {
        constexpr int NIT = Hh / 32;
        load_stageA(0, 0, g_W1h, Hh); CP_COMMIT();
        load_stageA(1, 1, g_W1h, Hh); CP_COMMIT();
        CP_WAIT1();
        __syncthreads();
#pragma unroll 1
        for (int k = 0; k < NIT; ++k) {
            const int st = k % NSTAGE;
            if (k + 2 < NIT) { load_stageA((k + 2) % NSTAGE, k + 2, g_W1h, Hh); CP_COMMIT(); }
            compute_iter(aLane + st * STAGE_BYTES,
                         dyn + SMEM_H0 + k * (32 * 272) + bLane, d);
            if (k + 2 < NIT)      { CP_WAIT1(); }
            else if (k + 1 < NIT) { CP_WAIT0(); }
            __syncthreads();
        }
    }
    epi_smem(dyn + SMEM_H1, b1);
    __syncthreads();

    // ================== Phase 3: y = (W2 @ h1 + b2) * mask ===================
    float* yp = g_y + (size_t)b * Oo * Nn;
#pragma unroll 1
    for (int oc = 0; oc < 4; ++oc) {
        const __half* W2c = g_W2h + (size_t)oc * 256 * Hh;
        zero_acc();
        constexpr int NIT = Hh / 32;
        load_stageA(0, 0, W2c, Hh); CP_COMMIT();
        load_stageA(1, 1, W2c, Hh); CP_COMMIT();
        CP_WAIT1();
        __syncthreads();
#pragma unroll 1
        for (int k = 0; k < NIT; ++k) {
            const int st = k % NSTAGE;
            if (k + 2 < NIT) { load_stageA((k + 2) % NSTAGE, k + 2, W2c, Hh); CP_COMMIT(); }
            compute_iter(aLane + st * STAGE_BYTES,
                         dyn + SMEM_H1 + k * (32 * 272) + bLane, d);
            if (k + 2 < NIT)      { CP_WAIT1(); }
            else if (k + 1 < NIT) { CP_WAIT0(); }
            __syncthreads();
        }
#pragma unroll
        for (int mf = 0; mf < 4; ++mf) {
            int o = oc * 256 + wm * 64 + mf * 16 + (lane >> 2);
#pragma unroll
            for (int nf = 0; nf < 4; ++nf) {
                int nl = wn * 32 + nf * 8 + (lane & 3) * 2;
                int n = n0 + nl;
                if (n < Nn) {
                    float mk0 = s_any[nl] ? 1.f : 0.f;
                    float mk1 = s_any[nl + 1] ? 1.f : 0.f;
                    if (o < Oo) {
                        float bs = b2[o];
                        *(float2*)(yp + (size_t)o * Nn + n) =
                            make_float2((d[mf][nf][0] + bs) * mk0, (d[mf][nf][1] + bs) * mk1);
                    }
                    if (o + 8 < Oo) {
                        float bs = b2[o + 8];
                        *(float2*)(yp + (size_t)(o + 8) * Nn + n) =
                            make_float2((d[mf][nf][2] + bs) * mk0, (d[mf][nf][3] + bs) * mk1);
                    }
                }
            }
        }
        __syncthreads();   // protect stage reuse across oc
    }
}

template <int WSEL>
__global__ void wconv_kernel(const float* __restrict__ W, int rows, int cols, int orows) {
    __half* outp = (WSEL == 0) ? g_W0h : (WSEL == 1) ? g_W1h : g_W2h;
    int i = blockIdx.x * 256 + threadIdx.x;
    if (i >= orows * cols) return;
    int r = i / cols, c = i - r * cols;
    outp[(size_t)r * cols + c] = __float2half_rn((r < rows) ? W[(size_t)r * cols + c] : 0.f);
}

__global__ void coef_kernel() {
    int b = threadIdx.x;
    if (b >= Bb) return;
    float s = 0.f, d10 = 0.f, d25 = 0.f, d50 = 0.f;
    for (int j = 0; j < 100; ++j) {
        s += g_mask[b * Nn + j];
        if (j == 9)  d10 = s;
        if (j == 24) d25 = s;
        if (j == 49) d50 = s;
    }
    float d100 = s;
    for (int j = 0; j < 100; ++j) {
        float w = 0.25f / d100;
        if (j < 50) w += 0.25f / d50;
        if (j < 25) w += 0.25f / d25;
        if (j < 10) w += 0.25f / d10;
        g_coef[b * 128 + j] = g_mask[b * Nn + j] * w;
    }
}

__global__ __launch_bounds__(256) void topk_kernel(float* __restrict__ out) {
    const int row = blockIdx.x, b = row / Oo, tid = threadIdx.x;
    __shared__ uint32_t su[Nn];
    __shared__ uint32_t hist[256];
    __shared__ uint32_t s_sel[2];
    __shared__ uint32_t s_cnt;
    __shared__ uint32_t buf[128];
    __shared__ uint32_t srt[128];
    __shared__ float partial[256];

    const float* yp = g_y + (size_t)row * Nn;
    for (int i = tid; i < Nn; i += 256) {
        uint32_t bits = __float_as_uint(yp[i]);
        su[i] = (bits & 0x80000000u) ? ~bits : (bits | 0x80000000u);
    }
    uint32_t prefix = 0, hiMask = 0;
    int K = 100;
    for (int level = 3; level >= 0; --level) {
        const int shift = level * 8;
        hist[tid] = 0;
        __syncthreads();
        for (int i = tid; i < Nn; i += 256) {
            uint32_t v = su[i];
            if ((v & hiMask) == prefix) atomicAdd(&hist[(v >> shift) & 255u], 1u);
        }
        __syncthreads();
        if (tid == 0) {
            int cum = 0, bin = 255;
            for (; bin > 0; --bin) {
                int c = (int)hist[bin];
                if (cum + c >= K) break;
                cum += c;
            }
            s_sel[0] = (uint32_t)bin; s_sel[1] = (uint32_t)(K - cum);
        }
        __syncthreads();
        prefix |= (s_sel[0] << shift);
        K = (int)s_sel[1];
        hiMask |= (0xFFu << shift);
        __syncthreads();
    }
    const uint32_t thr = prefix;
    if (tid == 0) s_cnt = 0;
    __syncthreads();
    for (int i = tid; i < Nn; i += 256) {
        uint32_t v = su[i];
        if (v > thr) {
            uint32_t idx = atomicAdd(&s_cnt, 1u);
            if (idx < 128u) buf[idx] = v;
        }
    }
    __syncthreads();
    int g = (int)min(s_cnt, 100u);
    for (int j = g + tid; j < 100; j += 256) buf[j] = thr;
    __syncthreads();
    if (tid < 100) {
        uint32_t v = buf[tid];
        int rank = 0;
#pragma unroll 4
        for (int j = 0; j < 100; ++j) {
            uint32_t w = buf[j];
            rank += (w > v) || (w == v && j < tid);
        }
        srt[rank] = v;
    }
    __syncthreads();
    float t = 0.f;
    if (tid < 100) {
        uint32_t u = srt[tid];
        uint32_t bits = (u & 0x80000000u) ? (u & 0x7FFFFFFFu) : ~u;
        t = __uint_as_float(bits) * g_coef[b * 128 + tid];
    }
    partial[tid] = t;
    __syncthreads();
    for (int s = 128; s > 0; s >>= 1) {
        if (tid < s) partial[tid] += partial[tid + s];
        __syncthreads();
    }
    if (tid == 0) out[row] = partial[0];
}

extern "C" void kernel_launch(void* const* d_in, const int* in_sizes, int n_in,
                              void* d_out, int out_size) {
    const float* x  = (const float*)d_in[0];
    const float* W0 = (const float*)d_in[1];
    const float* b0 = (const float*)d_in[2];
    const float* W1 = (const float*)d_in[3];
    const float* b1 = (const float*)d_in[4];
    const float* W2 = (const float*)d_in[5];
    const float* b2 = (const float*)d_in[6];
    float* out = (float*)d_out;
    (void)in_sizes; (void)n_in; (void)out_size;

    cudaFuncSetAttribute(fused_mlp, cudaFuncAttributeMaxDynamicSharedMemorySize, DYN_SMEM);

    wconv_kernel<0><<<(Hh * Cc + 255) / 256, 256>>>(W0, Hh, Cc, Hh);
    wconv_kernel<1><<<(Hh * Hh + 255) / 256, 256>>>(W1, Hh, Hh, Hh);
    wconv_kernel<2><<<(Op * Hh + 255) / 256, 256>>>(W2, Oo, Hh, Op);

    fused_mlp<<<dim3(NTILE, 1, Bb), 512, DYN_SMEM>>>(x, b0, b1, b2);

    coef_kernel<<<1, 32>>>();
    topk_kernel<<<Bb * Oo, 256>>>(out);
}